// round 12
// baseline (speedup 1.0000x reference)
#include <cuda_runtime.h>
#include <cstdint>

#define W 8192
#define H 2048
#define NPIX (W * H)
#define THREADS 512
#define PX_PER_BLOCK 2048
#define CHUNKS (PX_PER_BLOCK / THREADS)          // 4
#define NBLOCKS (NPIX / PX_PER_BLOCK)            // 8192
#define OUT_BYTES_PER_BLOCK (PX_PER_BLOCK * 12)  // 24576

#define FOV_SPAN     0.5235987755982988f
#define FOV_ABS_DOWN 0.2617993877991494f
#define TWO_PI       6.283185307179586f
#define PI_F         3.141592653589793f

// Rotation by 512 column steps: delta = 512 * 2*pi/8192 = pi/8
#define ROT_C 0.9238795325112867f
#define ROT_S 0.3826834323650898f

__device__ __forceinline__ uint32_t smem_u32(const void* p) {
    uint32_t a;
    asm("{ .reg .u64 t; cvta.to.shared.u64 t, %1; cvt.u32.u64 %0, t; }"
        : "=r"(a) : "l"(p));
    return a;
}

// Best-of-series combination:
//  - loads: scalar __ldcs depth reads, 16B lane stride (minimal L1 wavefronts,
//    front-batched MLP=4) — R6's load path, the best honest kernel window.
//    No mbarrier, no TMA-load serialization (R7 showed TMA loads cost ~1.5us).
//  - trig: inline sincosf + pi/8 Givens chain (no table prologue, 1-node graph)
//  - stores: smem staging + ONE 24KB cp.async.bulk per block (the R6 mechanism
//    that raised the sustained mixed R/W rate ~6%)
__global__ void __launch_bounds__(THREADS)
proj_to_pointcloud_kernel(const float* __restrict__ img, float* __restrict__ out) {
    __shared__ alignas(128) float s_out[PX_PER_BLOCK * 3];   // 24 KB

    int t = threadIdx.x;
    long blockBase = (long)blockIdx.x * PX_PER_BLOCK;        // 2048 | 8192: one row
    int row = (int)(blockBase >> 13);
    int j0  = (int)(blockBase & (W - 1));

    // Front-batch the 4 independent depth loads (streaming, evict-first).
    float d[CHUNKS];
    #pragma unroll
    for (int i = 0; i < CHUNKS; i++) {
        long px = blockBase + i * THREADS + t;
        d[i] = __ldcs(img + ((px << 2) + 3));
    }

    // Trig overlaps the load latency.
    float yaw = (float)(j0 + t) * (TWO_PI / (float)W) - PI_F;
    float s, c;
    sincosf(yaw, &s, &c);
    float pitch = (1.0f - (float)row / (float)H) * FOV_SPAN - FOV_ABS_DOWN;
    float sp = sinf(pitch);

    #pragma unroll
    for (int i = 0; i < CHUNKS; i++) {
        int p = i * THREADS + t;
        s_out[3 * p + 0] =  d[i] * c;        // stride-3 scalar STS: conflict-free
        s_out[3 * p + 1] = -d[i] * s;
        s_out[3 * p + 2] =  d[i] * sp;
        // advance yaw by 512 columns (pi/8)
        float cn = fmaf(c, ROT_C, -s * ROT_S);
        float sn = fmaf(s, ROT_C,  c * ROT_S);
        c = cn; s = sn;
    }

    __syncthreads();

    if (t == 0) {
        asm volatile("fence.proxy.async.shared::cta;" ::: "memory");
        asm volatile(
            "cp.async.bulk.global.shared::cta.bulk_group [%0], [%1], %2;"
            :: "l"(out + blockBase * 3), "r"(smem_u32(s_out)), "n"(OUT_BYTES_PER_BLOCK)
            : "memory");
        asm volatile("cp.async.bulk.commit_group;" ::: "memory");
        // Full completion before block exit: writes land inside block lifetime,
        // hidden by other resident blocks' compute.
        asm volatile("cp.async.bulk.wait_group 0;" ::: "memory");
    }
}

extern "C" void kernel_launch(void* const* d_in, const int* in_sizes, int n_in,
                              void* d_out, int out_size) {
    const float* img = (const float*)d_in[0];
    float* out = (float*)d_out;
    proj_to_pointcloud_kernel<<<NBLOCKS, THREADS>>>(img, out);
}